// round 13
// baseline (speedup 1.0000x reference)
#include <cuda_runtime.h>
#include <cuda_bf16.h>
#include <cstdint>

#define BATCH 512
#define FEAT  512
#define NBLK  128
#define NTHR  512

#define KH_LEN 256                          // K per CTA (half)
#define AS_STR 264                          // 256 + 8 bf16 pad
#define A_BYTES (64 * AS_STR * 2)           // 33792
#define B_BYTES (64 * AS_STR * 2)           // 33792
#define SMEM_TOTAL (A_BYTES + B_BYTES)      // 67584

__device__ __nv_bfloat16 g_fsb[BATCH * FEAT];
__device__ __nv_bfloat16 g_ftb[BATCH * FEAT];
__device__ float g_S0[BATCH * BATCH];       // k in [0,256) partial S
__device__ float g_S1[BATCH * BATCH];       // k in [256,512) partial S
__device__ unsigned g_entry = 0;            // monotonic: 128 per replay
__device__ unsigned g_cnv   = 0;            // monotonic: 128 per replay
__device__ unsigned g_band[8];              // monotonic: 16 per replay each
__device__ unsigned long long g_sum = 0;
__device__ unsigned g_done = 0;

#define SUM_SCALE 1073741824.0f             // 2^30
#define INV_SUM   (1.0 / 1073741824.0)

__global__ void __launch_bounds__(NTHR, 1) fused_kernel(const float* __restrict__ fs,
                                                        const float* __restrict__ ft,
                                                        float* __restrict__ out) {
    extern __shared__ __align__(16) char smem[];
    __nv_bfloat16 (*As)[AS_STR] = (__nv_bfloat16(*)[AS_STR])smem;
    __nv_bfloat16 (*Bs)[AS_STR] = (__nv_bfloat16(*)[AS_STR])(smem + A_BYTES);

    __shared__ float refs[4][8];
    __shared__ float wr[16][8];
    __shared__ unsigned replay_sm;

    const int tid   = threadIdx.x;
    const int bx    = blockIdx.x;           // 0..7 (nTile)
    const int by    = blockIdx.y;           // 0..7 (mTile band)
    const int kh    = blockIdx.z;           // 0..1 (K half)
    const int cid   = (kh << 6) | (by << 3) | bx;   // 0..127
    const int mTile = by * 64;
    const int nTile = bx * 64;
    const int kOff  = kh * KH_LEN;
    const int warp  = tid >> 5;
    const int lane  = tid & 31;
    const int wm    = warp & 3;
    const int wn    = warp >> 2;

    // replay index (race-free: increments of NEXT replay can't start until exit)
    if (tid == 0) replay_sm = atomicAdd(&g_entry, 1u) >> 7;

    // ================= Phase 0: convert fp32 -> bf16 ONCE ====================
    {
        const int idx = cid * NTHR + tid;    // 0..65535 float4 per tensor
        const float4 a = ((const float4*)fs)[idx];
        const float4 b = ((const float4*)ft)[idx];
        __nv_bfloat162 a0 = __floats2bfloat162_rn(a.x, a.y);
        __nv_bfloat162 a1 = __floats2bfloat162_rn(a.z, a.w);
        __nv_bfloat162 b0 = __floats2bfloat162_rn(b.x, b.y);
        __nv_bfloat162 b1 = __floats2bfloat162_rn(b.z, b.w);
        ((uint2*)g_fsb)[idx] = make_uint2(*(uint32_t*)&a0, *(uint32_t*)&a1);
        ((uint2*)g_ftb)[idx] = make_uint2(*(uint32_t*)&b0, *(uint32_t*)&b1);
    }
    __syncthreads();

    // ================= Global barrier: converts visible ======================
    if (tid == 0) {
        __threadfence();
        atomicAdd(&g_cnv, 1u);
        const unsigned target = replay_sm * 128u + 128u;
        while ((int)(*(volatile unsigned*)&g_cnv - target) < 0) {}
        __threadfence();
    }
    __syncthreads();

    // ================= Stage A and B bf16 tiles (no converts) ================
    // 64 rows x 256 bf16 = 2048 16B-chunks per tensor; 4 per thread.
    {
        #pragma unroll 4
        for (int v = 0; v < 4; v++) {
            const int idx = tid + v * NTHR;
            const int row = idx >> 5;        // 0..63
            const int c8  = idx & 31;        // 8-bf16 chunk
            const uint4 x = *(const uint4*)(g_fsb + (mTile + row) * FEAT + kOff + c8 * 8);
            *(uint4*)&As[row][c8 * 8] = x;
        }
        #pragma unroll 4
        for (int v = 0; v < 4; v++) {
            const int idx = tid + v * NTHR;
            const int row = idx >> 5;
            const int c8  = idx & 31;
            const uint4 x = *(const uint4*)(g_ftb + (nTile + row) * FEAT + kOff + c8 * 8);
            *(uint4*)&Bs[row][c8 * 8] = x;
        }
    }
    __syncthreads();

    // ================= Mainloop: 16 k16-steps per warp =======================
    float acc[2][4] = {};
    const int a_row = 16 * wm + (lane & 7) + ((lane >> 3) & 1) * 8;
    const int a_k8  = (lane >> 4) * 8;
    const int b_row = 16 * wn + (lane & 7) + (lane >> 4) * 8;
    const int b_k8  = ((lane >> 3) & 1) * 8;

    const uint32_t abase = (uint32_t)__cvta_generic_to_shared(&As[a_row][a_k8]);
    const uint32_t bbase = (uint32_t)__cvta_generic_to_shared(&Bs[b_row][b_k8]);

    #pragma unroll
    for (int kk = 0; kk < 16; kk++) {
        const uint32_t koff = kk * 32;
        uint32_t a0, a1, a2, a3, b0, b1, b2, b3;
        asm volatile("ldmatrix.sync.aligned.m8n8.x4.shared.b16 {%0,%1,%2,%3}, [%4];\n"
                     : "=r"(a0), "=r"(a1), "=r"(a2), "=r"(a3) : "r"(abase + koff));
        asm volatile("ldmatrix.sync.aligned.m8n8.x4.shared.b16 {%0,%1,%2,%3}, [%4];\n"
                     : "=r"(b0), "=r"(b1), "=r"(b2), "=r"(b3) : "r"(bbase + koff));
        asm volatile("mma.sync.aligned.m16n8k16.row.col.f32.bf16.bf16.f32 "
                     "{%0,%1,%2,%3}, {%4,%5,%6,%7}, {%8,%9}, {%0,%1,%2,%3};\n"
                     : "+f"(acc[0][0]), "+f"(acc[0][1]), "+f"(acc[0][2]), "+f"(acc[0][3])
                     : "r"(a0), "r"(a1), "r"(a2), "r"(a3), "r"(b0), "r"(b1));
        asm volatile("mma.sync.aligned.m16n8k16.row.col.f32.bf16.bf16.f32 "
                     "{%0,%1,%2,%3}, {%4,%5,%6,%7}, {%8,%9}, {%0,%1,%2,%3};\n"
                     : "+f"(acc[1][0]), "+f"(acc[1][1]), "+f"(acc[1][2]), "+f"(acc[1][3])
                     : "r"(a0), "r"(a1), "r"(a2), "r"(a3), "r"(b2), "r"(b3));
    }

    // ================= Epilogue: STG partial S to this K-half's buffer =======
    {
        const int g = lane >> 2, t = lane & 3;
        const int row0 = mTile + 16 * wm + g;
        float* dst = kh ? g_S1 : g_S0;
        #pragma unroll
        for (int h = 0; h < 2; h++) {
            const int col = nTile + 16 * wn + t * 2 + 8 * h;
            *(float2*)&dst[row0 * BATCH + col]       = make_float2(acc[h][0], acc[h][1]);
            *(float2*)&dst[(row0 + 8) * BATCH + col] = make_float2(acc[h][2], acc[h][3]);
        }
    }
    __syncthreads();

    // ================= Band-local barrier (16 CTAs: 8 bx x 2 kh) =============
    if (tid == 0) {
        __threadfence();
        atomicAdd(&g_band[by], 1u);
        const unsigned target = replay_sm * 16u + 16u;
        while ((int)(*(volatile unsigned*)&g_band[by] - target) < 0) {}
        __threadfence();
    }
    __syncthreads();

    // ================= Phase 2: 4 rows per CTA, 128 thr/row ==================
    const int row_l = tid >> 7;
    const int c     = tid & 127;
    const int r     = by * 64 + (kh * 8 + bx) * 4 + row_l;
    const float4 u0 = ((const float4*)(g_S0 + r * BATCH))[c];
    const float4 u1 = ((const float4*)(g_S1 + r * BATCH))[c];
    const float4 v  = make_float4(u0.x + u1.x, u0.y + u1.y, u0.z + u1.z, u0.w + u1.w);

    const int rc0 = (r & ~7) >> 2;
    if (c == rc0)     *(float4*)&refs[row_l][0] = v;
    if (c == rc0 + 1) *(float4*)&refs[row_l][4] = v;
    __syncthreads();

    float p[8];
    #pragma unroll
    for (int j = 0; j < 8; j++) p[j] = refs[row_l][j];

    float s8[8];
    #pragma unroll
    for (int j = 0; j < 8; j++) {
        s8[j] = fmaxf(v.x - p[j], 0.f) + fmaxf(v.y - p[j], 0.f)
              + fmaxf(v.z - p[j], 0.f) + fmaxf(v.w - p[j], 0.f);
    }
    #pragma unroll
    for (int o = 16; o > 0; o >>= 1)
        #pragma unroll
        for (int j = 0; j < 8; j++)
            s8[j] += __shfl_down_sync(0xffffffffu, s8[j], o);
    if (lane == 0) {
        #pragma unroll
        for (int j = 0; j < 8; j++) wr[warp][j] = s8[j];
    }
    __syncthreads();

    float ratio = 0.f;
    if (tid < 32) {
        const int rl = tid >> 3, j = tid & 7;
        const float rk = 1.f + wr[rl * 4][j] + wr[rl * 4 + 1][j]
                             + wr[rl * 4 + 2][j] + wr[rl * 4 + 3][j];
        const float pj = refs[rl][j];
        float ps = 0.f;
        #pragma unroll
        for (int k = 0; k < 8; k++) ps += fmaxf(refs[rl][k] - pj, 0.f);
        ratio = (1.f + ps) / rk;
        #pragma unroll
        for (int o = 16; o > 0; o >>= 1)
            ratio += __shfl_down_sync(0xffffffffu, ratio, o);
    }

    // ================= Deterministic fixed-point tail ========================
    if (tid == 0) {
        atomicAdd(&g_sum, (unsigned long long)llrintf(ratio * SUM_SCALE));
        __threadfence();
        const unsigned prev = atomicAdd(&g_done, 1);
        if (prev == NBLK - 1) {
            const unsigned long long tot = *((volatile unsigned long long*)&g_sum);
            out[0] = (float)(1.0 - ((double)tot * INV_SUM) * (1.0 / 4096.0));
            g_sum  = 0;
            g_done = 0;
        }
    }
}

extern "C" void kernel_launch(void* const* d_in, const int* in_sizes, int n_in,
                              void* d_out, int out_size) {
    const float* fs = (const float*)d_in[0];
    const float* ft = (const float*)d_in[1];
    float* out = (float*)d_out;

    cudaFuncSetAttribute(fused_kernel,
                         cudaFuncAttributeMaxDynamicSharedMemorySize, SMEM_TOTAL);
    fused_kernel<<<dim3(8, 8, 2), NTHR, SMEM_TOTAL>>>(fs, ft, out);
}